// round 1
// baseline (speedup 1.0000x reference)
#include <cuda_runtime.h>
#include <math.h>

#define L       16384
#define NMODES  64
#define THREADS 512
#define SW(a) ((a) ^ (((a) >> 4) & 15))

__device__ float2 g_F[L];
__device__ float2 g_Hc[L];

__device__ __forceinline__ float2 cmulf(float2 a, float2 b) {
    return make_float2(a.x*b.x - a.y*b.y, a.x*b.y + a.y*b.x);
}

// ---------------------------------------------------------------------------
// Precompute: F[k] = sum_n C_n (1 - r_n^L) / (1 - r_n w^-k), r_n = exp(dt*Lam_n)
// ---------------------------------------------------------------------------
__global__ void k_precompute_F(const float* __restrict__ Lr, const float* __restrict__ Li,
                               const float* __restrict__ wr, const float* __restrict__ wi,
                               const float* __restrict__ dtp) {
    int k = blockIdx.x * blockDim.x + threadIdx.x;
    float dt = dtp[0];
    float s, c;
    sincospif(2.0f * (float)k / (float)L, &s, &c);   // w^-k = (c, -s)
    float accx = 0.f, accy = 0.f;
    for (int n = 0; n < NMODES; n++) {
        float lr = Lr[n], li = Li[n];
        float zr = dt * lr, zi = dt * li;
        float er = expf(zr);
        float sz, cz; sincosf(zi, &sz, &cz);
        float rr = er * cz, ri = er * sz;
        // E = 1 - r^L  (r^L underflows for the given init; guarded for generality)
        float rLm = expf(zr * (float)L);
        float Er = 1.0f, Ei = 0.0f;
        if (rLm > 1e-35f) {
            float sa, ca; sincosf(zi * (float)L, &sa, &ca);
            Er = 1.0f - rLm * ca; Ei = -rLm * sa;
        }
        // C = w * (r - 1) / Lambda
        float emr = rr - 1.0f, emi = ri;
        float il2 = 1.0f / (lr*lr + li*li);
        float qr = (emr*lr + emi*li) * il2;
        float qi = (emi*lr - emr*li) * il2;
        float Cr = wr[n]*qr - wi[n]*qi;
        float Ci = wr[n]*qi + wi[n]*qr;
        float cer = Cr*Er - Ci*Ei;
        float cei = Cr*Ei + Ci*Er;
        // den = 1 - r * w^-k
        float dr = 1.0f - (rr*c + ri*s);
        float di = -(ri*c - rr*s);
        float inv = 1.0f / (dr*dr + di*di);
        accx += (cer*dr + cei*di) * inv;
        accy += (cei*dr - cer*di) * inv;
    }
    g_F[k] = make_float2(accx, accy);
}

// Hc[k] = conj(H[k]) / L,  H[k] = (F[k] + conj(F[L-k])) / 2
__global__ void k_combine_H() {
    int k = blockIdx.x * blockDim.x + threadIdx.x;
    float2 Fk = g_F[k];
    float2 Fm = g_F[(L - k) & (L - 1)];
    const float sc = 1.0f / (2.0f * (float)L);
    g_Hc[k] = make_float2((Fk.x + Fm.x) * sc, (Fm.y - Fk.y) * sc);
}

// ---------------------------------------------------------------------------
// In-place (sync-separated) Stockham FFT, N = 16384 = 16*16*16*4, 512 threads
// ---------------------------------------------------------------------------
__device__ __forceinline__ void dft4(float2& a, float2& b, float2& c, float2& d) {
    float2 t0 = make_float2(a.x + c.x, a.y + c.y);
    float2 t1 = make_float2(a.x - c.x, a.y - c.y);
    float2 t2 = make_float2(b.x + d.x, b.y + d.y);
    float2 t3 = make_float2(b.x - d.x, b.y - d.y);
    a = make_float2(t0.x + t2.x, t0.y + t2.y);
    c = make_float2(t0.x - t2.x, t0.y - t2.y);
    b = make_float2(t1.x + t3.y, t1.y - t3.x);   // t1 - i*t3
    d = make_float2(t1.x - t3.y, t1.y + t3.x);   // t1 + i*t3
}

// In-place DFT-16. Output b[u] lands at slot 4*(u&3) + (u>>2) (digit swap).
__device__ __forceinline__ void dft16(float2* a) {
    const float C1 = 0.92387953251128675613f;
    const float S1 = 0.38268343236508977173f;
    const float HS = 0.70710678118654752440f;
    dft4(a[0], a[4], a[8],  a[12]);
    dft4(a[1], a[5], a[9],  a[13]);
    dft4(a[2], a[6], a[10], a[14]);
    dft4(a[3], a[7], a[11], a[15]);
    const float2 W1 = make_float2( C1, -S1);
    const float2 W2 = make_float2( HS, -HS);
    const float2 W3 = make_float2( S1, -C1);
    const float2 W6 = make_float2(-HS, -HS);
    const float2 W9 = make_float2(-C1,  S1);
    a[5]  = cmulf(a[5],  W1);
    a[6]  = cmulf(a[6],  W2);
    a[7]  = cmulf(a[7],  W3);
    a[9]  = cmulf(a[9],  W2);
    a[10] = make_float2(a[10].y, -a[10].x);      // * (-i)
    a[11] = cmulf(a[11], W6);
    a[13] = cmulf(a[13], W3);
    a[14] = cmulf(a[14], W6);
    a[15] = cmulf(a[15], W9);
    dft4(a[0],  a[1],  a[2],  a[3]);
    dft4(a[4],  a[5],  a[6],  a[7]);
    dft4(a[8],  a[9],  a[10], a[11]);
    dft4(a[12], a[13], a[14], a[15]);
}

__device__ __forceinline__ void bf16_store(float2* sm, float2* a, int i, int mshift, int l) {
    int j = i >> mshift;
    int k = i & ((1 << mshift) - 1);
    dft16(a);
    float s1, c1;
    sincospif(-(float)j / (8.0f * (float)l), &s1, &c1);   // w1 = exp(-2*pi*i*j/(16*l))
    float2 w1 = make_float2(c1, s1);
    int base = k + ((16 * j) << mshift);
    sm[SW(base)] = a[0];
    float2 w = w1;
#pragma unroll
    for (int u = 1; u < 16; u++) {
        int slot = ((u & 3) << 2) | (u >> 2);
        sm[SW(base + (u << mshift))] = cmulf(a[slot], w);
        w = cmulf(w, w1);
    }
}

__device__ __forceinline__ void fft16384(float2* sm, int t) {
    float2 A[16], Bv[16];
#pragma unroll
    for (int s = 0; s < 3; s++) {
        const int mshift = 4 * s;
        const int l = (s == 0) ? 1024 : ((s == 1) ? 64 : 4);
        const int i0 = t, i1 = t + 512;
#pragma unroll
        for (int tt = 0; tt < 16; tt++) A[tt]  = sm[SW(i0 + 1024 * tt)];
#pragma unroll
        for (int tt = 0; tt < 16; tt++) Bv[tt] = sm[SW(i1 + 1024 * tt)];
        __syncthreads();                 // all reads done before any writes
        bf16_store(sm, A,  i0, mshift, l);
        bf16_store(sm, Bv, i1, mshift, l);
        __syncthreads();                 // all writes done before next reads
    }
    // final radix-4 stage: l = 1, twiddle-free, in-place per butterfly
#pragma unroll
    for (int b = 0; b < 8; b++) {
        int i = t + 512 * b;
        float2 p0 = sm[SW(i)];
        float2 p1 = sm[SW(i + 4096)];
        float2 p2 = sm[SW(i + 8192)];
        float2 p3 = sm[SW(i + 12288)];
        dft4(p0, p1, p2, p3);
        sm[SW(i)]         = p0;
        sm[SW(i + 4096)]  = p1;
        sm[SW(i + 8192)]  = p2;
        sm[SW(i + 12288)] = p3;
    }
    __syncthreads();
}

// ---------------------------------------------------------------------------
// Main: one CTA convolves two rows packed as one complex sequence.
//   Z = FFT(xa + i*xb); S = Hc * conj(Z); out = FFT(S); ya = Re, yb = -Im
// ---------------------------------------------------------------------------
__global__ __launch_bounds__(THREADS, 1)
void k_fftconv(const float* __restrict__ x, float* __restrict__ y) {
    extern __shared__ float2 sm[];
    const int t = threadIdx.x;
    const size_t row = (size_t)blockIdx.x * 2;
    const float* xa = x + row * L;
    const float* xb = xa + L;
#pragma unroll
    for (int b = 0; b < 32; b++) {
        int idx = t + THREADS * b;
        sm[SW(idx)] = make_float2(xa[idx], xb[idx]);
    }
    __syncthreads();
    fft16384(sm, t);
#pragma unroll
    for (int b = 0; b < 32; b++) {
        int k = t + THREADS * b;
        float2 z = sm[SW(k)];
        float2 h = g_Hc[k];
        // h * conj(z)
        sm[SW(k)] = make_float2(h.x*z.x + h.y*z.y, h.y*z.x - h.x*z.y);
    }
    __syncthreads();
    fft16384(sm, t);
    float* ya = y + row * L;
    float* yb = ya + L;
#pragma unroll
    for (int b = 0; b < 32; b++) {
        int idx = t + THREADS * b;
        float2 v = sm[SW(idx)];
        ya[idx] =  v.x;
        yb[idx] = -v.y;
    }
}

// ---------------------------------------------------------------------------
extern "C" void kernel_launch(void* const* d_in, const int* in_sizes, int n_in,
                              void* d_out, int out_size) {
    const float* x  = (const float*)d_in[0];
    const float* Lr = (const float*)d_in[1];
    const float* Li = (const float*)d_in[2];
    const float* wr = (const float*)d_in[3];
    const float* wi = (const float*)d_in[4];
    const float* dt = (const float*)d_in[5];
    float* y = (float*)d_out;

    cudaFuncSetAttribute(k_fftconv, cudaFuncAttributeMaxDynamicSharedMemorySize, L * sizeof(float2));

    k_precompute_F<<<L / 256, 256>>>(Lr, Li, wr, wi, dt);
    k_combine_H<<<L / 256, 256>>>();
    k_fftconv<<<(8 * 256) / 2, THREADS, L * sizeof(float2)>>>(x, y);
}

// round 3
// speedup vs baseline: 1.0473x; 1.0473x over previous
#include <cuda_runtime.h>
#include <math.h>

#define L       16384
#define NMODES  64
#define THREADS 1024
#define SW(a) ((a) ^ (((a) >> 4) & 15))

__device__ float2 g_Hc[L];
__device__ float4 g_mode[NMODES];

// ---------------------------------------------------------------------------
// Packed f32x2 helpers (Blackwell): ptxas does NOT auto-pack — do it manually.
// ---------------------------------------------------------------------------
union F2U { float2 f; unsigned long long u; };

__device__ __forceinline__ float2 f2add(float2 a, float2 b) {
    F2U x, y, r; x.f = a; y.f = b;
    asm("add.rn.f32x2 %0, %1, %2;" : "=l"(r.u) : "l"(x.u), "l"(y.u));
    return r.f;
}
__device__ __forceinline__ float2 f2fma(float2 a, float2 b, float2 c) {  // a*b + c
    F2U x, y, z, r; x.f = a; y.f = b; z.f = c;
    asm("fma.rn.f32x2 %0, %1, %2, %3;" : "=l"(r.u) : "l"(x.u), "l"(y.u), "l"(z.u));
    return r.f;
}
__device__ __forceinline__ float2 f2sub(float2 a, float2 b) {  // a - b (exact: b*(-1)+a)
    return f2fma(b, make_float2(-1.0f, -1.0f), a);
}

__device__ __forceinline__ float2 cmulf(float2 a, float2 b) {
    return make_float2(a.x*b.x - a.y*b.y, a.x*b.y + a.y*b.x);
}

// ---------------------------------------------------------------------------
// Precompute: per-mode constants (k-independent part)
//   r = exp(dt*Lambda), ce = w*(r-1)/Lambda * (1 - r^L)
// ---------------------------------------------------------------------------
__global__ void k_modes(const float* __restrict__ Lr, const float* __restrict__ Li,
                        const float* __restrict__ wr, const float* __restrict__ wi,
                        const float* __restrict__ dtp) {
    int n = threadIdx.x;
    float dt = dtp[0];
    float lr = Lr[n], li = Li[n];
    float zr = dt * lr, zi = dt * li;
    float er = expf(zr);
    float sz, cz; sincosf(zi, &sz, &cz);
    float rr = er * cz, ri = er * sz;
    float rLm = expf(zr * (float)L);
    float Er = 1.0f, Ei = 0.0f;
    if (rLm > 1e-35f) {
        float sa, ca; sincosf(zi * (float)L, &sa, &ca);
        Er = 1.0f - rLm * ca; Ei = -rLm * sa;
    }
    float emr = rr - 1.0f, emi = ri;
    float il2 = 1.0f / (lr*lr + li*li);
    float qr = (emr*lr + emi*li) * il2;
    float qi = (emi*lr - emr*li) * il2;
    float Cr = wr[n]*qr - wi[n]*qi;
    float Ci = wr[n]*qi + wi[n]*qr;
    float cer = Cr*Er - Ci*Ei;
    float cei = Cr*Ei + Ci*Er;
    g_mode[n] = make_float4(rr, ri, cer, cei);
}

// Hc[k] = conj((F[k] + conj(F[L-k]))/2) / L ; each thread does k and L-k at once
// (omega^{-(L-k)} = conj(omega^{-k}) -> just negate s).
__global__ void k_hc() {
    __shared__ float4 md[NMODES];
    int t = threadIdx.x;
    if (t < NMODES) md[t] = g_mode[t];
    __syncthreads();
    int kp = blockIdx.x * blockDim.x + t;
    if (kp > L / 2) return;
    float s, c;
    sincospif(2.0f * (float)kp / (float)L, &s, &c);
    float px = 0.f, py = 0.f, mx = 0.f, my = 0.f;
#pragma unroll 4
    for (int n = 0; n < NMODES; n++) {
        float4 m = md[n];
        float rc = m.x * c, rs = m.y * s;
        float rrs = m.x * s, ric = m.y * c;
        // F[kp] (uses +s)
        float dr = 1.0f - (rc + rs);
        float di = rrs - ric;
        float inv = 1.0f / (dr*dr + di*di);
        px += (m.z*dr + m.w*di) * inv;
        py += (m.w*dr - m.z*di) * inv;
        // F[L-kp] (uses -s)
        float dr2 = 1.0f - (rc - rs);
        float di2 = -rrs - ric;
        float inv2 = 1.0f / (dr2*dr2 + di2*di2);
        mx += (m.z*dr2 + m.w*di2) * inv2;
        my += (m.w*dr2 - m.z*di2) * inv2;
    }
    const float sc = 1.0f / (2.0f * (float)L);
    g_Hc[kp]               = make_float2((px + mx) * sc, (my - py) * sc);
    g_Hc[(L - kp) & (L-1)] = make_float2((px + mx) * sc, (py - my) * sc);
}

// ---------------------------------------------------------------------------
// Stockham FFT, N = 16384 = 16*16*16*4, 1024 threads, one butterfly/thread
// ---------------------------------------------------------------------------
__device__ __forceinline__ void dft4(float2& a, float2& b, float2& c, float2& d) {
    float2 t0 = f2add(a, c);
    float2 t1 = f2sub(a, c);
    float2 t2 = f2add(b, d);
    float2 t3 = f2sub(b, d);
    a = f2add(t0, t2);
    c = f2sub(t0, t2);
    float2 t3r = make_float2(t3.y, -t3.x);   // -i * t3
    b = f2add(t1, t3r);                      // t1 - i*t3
    d = f2sub(t1, t3r);                      // t1 + i*t3
}

// In-place DFT-16. Output b[u] lands at slot 4*(u&3) + (u>>2) (digit swap).
__device__ __forceinline__ void dft16(float2* a) {
    const float C1 = 0.92387953251128675613f;
    const float S1 = 0.38268343236508977173f;
    const float HS = 0.70710678118654752440f;
    dft4(a[0], a[4], a[8],  a[12]);
    dft4(a[1], a[5], a[9],  a[13]);
    dft4(a[2], a[6], a[10], a[14]);
    dft4(a[3], a[7], a[11], a[15]);
    const float2 W1 = make_float2( C1, -S1);
    const float2 W2 = make_float2( HS, -HS);
    const float2 W3 = make_float2( S1, -C1);
    const float2 W6 = make_float2(-HS, -HS);
    const float2 W9 = make_float2(-C1,  S1);
    a[5]  = cmulf(a[5],  W1);
    a[6]  = cmulf(a[6],  W2);
    a[7]  = cmulf(a[7],  W3);
    a[9]  = cmulf(a[9],  W2);
    a[10] = make_float2(a[10].y, -a[10].x);      // * (-i)
    a[11] = cmulf(a[11], W6);
    a[13] = cmulf(a[13], W3);
    a[14] = cmulf(a[14], W6);
    a[15] = cmulf(a[15], W9);
    dft4(a[0],  a[1],  a[2],  a[3]);
    dft4(a[4],  a[5],  a[6],  a[7]);
    dft4(a[8],  a[9],  a[10], a[11]);
    dft4(a[12], a[13], a[14], a[15]);
}

template<int MSHIFT>
__device__ __forceinline__ void stage(float2* sm, int t, float2 w1) {
    float2 a[16];
#pragma unroll
    for (int tt = 0; tt < 16; tt++) a[tt] = sm[SW(t + 1024 * tt)];
    __syncthreads();                 // all reads done before any writes (in-place)
    dft16(a);
    int j = t >> MSHIFT;
    int k = t & ((1 << MSHIFT) - 1);
    int base = k + ((16 * j) << MSHIFT);
    sm[SW(base)] = a[0];
    float2 w = w1;
#pragma unroll
    for (int u = 1; u < 16; u++) {
        int slot = ((u & 3) << 2) | (u >> 2);
        sm[SW(base + (u << MSHIFT))] = cmulf(a[slot], w);
        w = cmulf(w, w1);
    }
    __syncthreads();
}

__device__ __forceinline__ void fft16384(float2* sm, int t,
                                         float2 w0, float2 w1, float2 w2) {
    stage<0>(sm, t, w0);
    stage<4>(sm, t, w1);
    stage<8>(sm, t, w2);
    // final radix-4 stage: l = 1, twiddle-free, in-place per butterfly
#pragma unroll
    for (int b = 0; b < 4; b++) {
        int i = t + 1024 * b;
        float2 p0 = sm[SW(i)];
        float2 p1 = sm[SW(i + 4096)];
        float2 p2 = sm[SW(i + 8192)];
        float2 p3 = sm[SW(i + 12288)];
        dft4(p0, p1, p2, p3);
        sm[SW(i)]         = p0;
        sm[SW(i + 4096)]  = p1;
        sm[SW(i + 8192)]  = p2;
        sm[SW(i + 12288)] = p3;
    }
    __syncthreads();
}

// ---------------------------------------------------------------------------
// Main: one CTA convolves two rows packed as one complex sequence.
//   Z = FFT(xa + i*xb); S = Hc * conj(Z); out = FFT(S); ya = Re, yb = -Im
// ---------------------------------------------------------------------------
__global__ __launch_bounds__(THREADS, 1)
void k_fftconv(const float* __restrict__ x, float* __restrict__ y) {
    extern __shared__ float2 sm[];
    const int t = threadIdx.x;
    const size_t row = (size_t)blockIdx.x * 2;
    const float4* __restrict__ xa4 = (const float4*)(x + row * L);
    const float4* __restrict__ xb4 = (const float4*)(x + (row + 1) * L);

#pragma unroll
    for (int b = 0; b < 4; b++) {
        int i4 = t + 1024 * b;
        float4 va = xa4[i4];
        float4 vb = xb4[i4];
        int idx = i4 * 4;
        sm[SW(idx)]     = make_float2(va.x, vb.x);
        sm[SW(idx + 1)] = make_float2(va.y, vb.y);
        sm[SW(idx + 2)] = make_float2(va.z, vb.z);
        sm[SW(idx + 3)] = make_float2(va.w, vb.w);
    }

    // Stage base twiddles: identical for both FFT passes — compute once.
    float2 w0, w1, w2;
    sincospif(-(float)t        / 8192.0f, &w0.y, &w0.x);
    sincospif(-(float)(t >> 4) / 512.0f,  &w1.y, &w1.x);
    sincospif(-(float)(t >> 8) / 32.0f,   &w2.y, &w2.x);

    __syncthreads();
    fft16384(sm, t, w0, w1, w2);

#pragma unroll
    for (int b = 0; b < 16; b++) {
        int kk = t + 1024 * b;
        float2 z = sm[SW(kk)];
        float2 h = g_Hc[kk];
        // h * conj(z)
        sm[SW(kk)] = make_float2(h.x*z.x + h.y*z.y, h.y*z.x - h.x*z.y);
    }
    __syncthreads();
    fft16384(sm, t, w0, w1, w2);

    float4* __restrict__ ya4 = (float4*)(y + row * L);
    float4* __restrict__ yb4 = (float4*)(y + (row + 1) * L);
#pragma unroll
    for (int b = 0; b < 4; b++) {
        int i4 = t + 1024 * b;
        int idx = i4 * 4;
        float2 v0 = sm[SW(idx)];
        float2 v1 = sm[SW(idx + 1)];
        float2 v2 = sm[SW(idx + 2)];
        float2 v3 = sm[SW(idx + 3)];
        ya4[i4] = make_float4(v0.x, v1.x, v2.x, v3.x);
        yb4[i4] = make_float4(-v0.y, -v1.y, -v2.y, -v3.y);
    }
}

// ---------------------------------------------------------------------------
extern "C" void kernel_launch(void* const* d_in, const int* in_sizes, int n_in,
                              void* d_out, int out_size) {
    const float* x  = (const float*)d_in[0];
    const float* Lr = (const float*)d_in[1];
    const float* Li = (const float*)d_in[2];
    const float* wr = (const float*)d_in[3];
    const float* wi = (const float*)d_in[4];
    const float* dt = (const float*)d_in[5];
    float* y = (float*)d_out;

    cudaFuncSetAttribute(k_fftconv, cudaFuncAttributeMaxDynamicSharedMemorySize,
                         L * sizeof(float2));

    k_modes<<<1, NMODES>>>(Lr, Li, wr, wi, dt);
    k_hc<<<(L / 2 + 1 + 127) / 128, 128>>>();
    k_fftconv<<<(8 * 256) / 2, THREADS, L * sizeof(float2)>>>(x, y);
}

// round 4
// speedup vs baseline: 1.1061x; 1.0562x over previous
#include <cuda_runtime.h>
#include <math.h>

#define L       16384
#define NMODES  64
#define THREADS 1024
#define SW(a) ((a) ^ (((a) >> 4) & 15))

__device__ float2 g_Hc[L];     // H[k]/L stored at scrambled position P(k)
__device__ float4 g_mode[NMODES];

// ---------------------------------------------------------------------------
// Packed f32x2 helpers
// ---------------------------------------------------------------------------
union F2U { float2 f; unsigned long long u; };

__device__ __forceinline__ float2 f2add(float2 a, float2 b) {
    F2U x, y, r; x.f = a; y.f = b;
    asm("add.rn.f32x2 %0, %1, %2;" : "=l"(r.u) : "l"(x.u), "l"(y.u));
    return r.f;
}
__device__ __forceinline__ float2 f2fma(float2 a, float2 b, float2 c) {
    F2U x, y, z, r; x.f = a; y.f = b; z.f = c;
    asm("fma.rn.f32x2 %0, %1, %2, %3;" : "=l"(r.u) : "l"(x.u), "l"(y.u), "l"(z.u));
    return r.f;
}
__device__ __forceinline__ float2 f2sub(float2 a, float2 b) {
    return f2fma(b, make_float2(-1.0f, -1.0f), a);
}
__device__ __forceinline__ float2 cmulf(float2 a, float2 b) {
    return make_float2(a.x*b.x - a.y*b.y, a.x*b.y + a.y*b.x);
}

// ---------------------------------------------------------------------------
// Precompute: per-mode constants
// ---------------------------------------------------------------------------
__global__ void k_modes(const float* __restrict__ Lr, const float* __restrict__ Li,
                        const float* __restrict__ wr, const float* __restrict__ wi,
                        const float* __restrict__ dtp) {
    int n = threadIdx.x;
    float dt = dtp[0];
    float lr = Lr[n], li = Li[n];
    float zr = dt * lr, zi = dt * li;
    float er = expf(zr);
    float sz, cz; sincosf(zi, &sz, &cz);
    float rr = er * cz, ri = er * sz;
    float rLm = expf(zr * (float)L);
    float Er = 1.0f, Ei = 0.0f;
    if (rLm > 1e-35f) {
        float sa, ca; sincosf(zi * (float)L, &sa, &ca);
        Er = 1.0f - rLm * ca; Ei = -rLm * sa;
    }
    float emr = rr - 1.0f, emi = ri;
    float il2 = 1.0f / (lr*lr + li*li);
    float qr = (emr*lr + emi*li) * il2;
    float qi = (emi*lr - emr*li) * il2;
    float Cr = wr[n]*qr - wi[n]*qi;
    float Ci = wr[n]*qi + wi[n]*qr;
    float cer = Cr*Er - Ci*Ei;
    float cei = Cr*Ei + Ci*Er;
    g_mode[n] = make_float4(rr, ri, cer, cei);
}

// Scrambled position of frequency k under DIF(16,16,16,4):
// P(k) = 1024*k0 + 64*k1 + 4*k2 + k3,  k = k0 + 16k1 + 256k2 + 4096k3
__device__ __forceinline__ int scramble(int k) {
    return ((k & 15) << 10) | (((k >> 4) & 15) << 6) | (((k >> 8) & 15) << 2) | (k >> 12);
}

// g_Hc[P(k)] = H[k]/L (no conj: second pass is a true inverse transform)
__global__ void k_hc() {
    __shared__ float4 md[NMODES];
    int t = threadIdx.x;
    if (t < NMODES) md[t] = g_mode[t];
    __syncthreads();
    int kp = blockIdx.x * blockDim.x + t;
    if (kp > L / 2) return;
    float s, c;
    sincospif(2.0f * (float)kp / (float)L, &s, &c);
    float px = 0.f, py = 0.f, mx = 0.f, my = 0.f;
#pragma unroll 4
    for (int n = 0; n < NMODES; n++) {
        float4 m = md[n];
        float rc = m.x * c, rs = m.y * s;
        float rrs = m.x * s, ric = m.y * c;
        float dr = 1.0f - (rc + rs);
        float di = rrs - ric;
        float inv = 1.0f / (dr*dr + di*di);
        px += (m.z*dr + m.w*di) * inv;
        py += (m.w*dr - m.z*di) * inv;
        float dr2 = 1.0f - (rc - rs);
        float di2 = -rrs - ric;
        float inv2 = 1.0f / (dr2*dr2 + di2*di2);
        mx += (m.z*dr2 + m.w*di2) * inv2;
        my += (m.w*dr2 - m.z*di2) * inv2;
    }
    const float sc = 1.0f / (2.0f * (float)L);
    // H[kp] = ((px+mx) + i(py-my))/2 ;  H[L-kp] = ((px+mx) + i(my-py))/2
    g_Hc[scramble(kp)]                = make_float2((px + mx) * sc, (py - my) * sc);
    g_Hc[scramble((L - kp) & (L-1))]  = make_float2((px + mx) * sc, (my - py) * sc);
}

// ---------------------------------------------------------------------------
// Radix-4 / radix-16 butterflies, forward (INV=false) and conjugate (INV=true)
// ---------------------------------------------------------------------------
template<bool INV>
__device__ __forceinline__ void dft4(float2& a, float2& b, float2& c, float2& d) {
    float2 t0 = f2add(a, c);
    float2 t1 = f2sub(a, c);
    float2 t2 = f2add(b, d);
    float2 t3 = f2sub(b, d);
    a = f2add(t0, t2);
    c = f2sub(t0, t2);
    float2 t3r = INV ? make_float2(-t3.y, t3.x)     // +i*t3
                     : make_float2(t3.y, -t3.x);    // -i*t3
    b = f2add(t1, t3r);
    d = f2sub(t1, t3r);
}

// In-place DFT-16 (conjugate transform when INV). Output u lands at
// slot sig(u) = 4*(u&3) + (u>>2).
template<bool INV>
__device__ __forceinline__ void dft16(float2* a) {
    const float C1 = 0.92387953251128675613f;
    const float S1 = 0.38268343236508977173f;
    const float HS = 0.70710678118654752440f;
    const float sg = INV ? 1.0f : -1.0f;
    dft4<INV>(a[0], a[4], a[8],  a[12]);
    dft4<INV>(a[1], a[5], a[9],  a[13]);
    dft4<INV>(a[2], a[6], a[10], a[14]);
    dft4<INV>(a[3], a[7], a[11], a[15]);
    const float2 W1 = make_float2( C1, sg*S1);
    const float2 W2 = make_float2( HS, sg*HS);
    const float2 W3 = make_float2( S1, sg*C1);
    const float2 W6 = make_float2(-HS, sg*HS);
    const float2 W9 = make_float2(-C1, -sg*S1);
    a[5]  = cmulf(a[5],  W1);
    a[6]  = cmulf(a[6],  W2);
    a[7]  = cmulf(a[7],  W3);
    a[9]  = cmulf(a[9],  W2);
    a[10] = INV ? make_float2(-a[10].y, a[10].x)    // * (+i)
                : make_float2(a[10].y, -a[10].x);   // * (-i)
    a[11] = cmulf(a[11], W6);
    a[13] = cmulf(a[13], W3);
    a[14] = cmulf(a[14], W6);
    a[15] = cmulf(a[15], W9);
    dft4<INV>(a[0],  a[1],  a[2],  a[3]);
    dft4<INV>(a[4],  a[5],  a[6],  a[7]);
    dft4<INV>(a[8],  a[9],  a[10], a[11]);
    dft4<INV>(a[12], a[13], a[14], a[15]);
}

__device__ __constant__ int SIGTAB[16] = {0,4,8,12,1,5,9,13,2,6,10,14,3,7,11,15};

// DIF middle stage (forward): read 16 @ base+(m<<SIG), dft16, output twiddle
// W^{s*u} (w = exp(-2*pi*i*s/(16*S))), write back to the SAME slots.
template<int SIG>
__device__ __forceinline__ void dif_stage(float2* sm, int t) {
    const int S = 1 << SIG;
    int s = t & (S - 1);
    int base = ((t >> SIG) << (SIG + 4)) | s;
    float2 a[16];
#pragma unroll
    for (int m = 0; m < 16; m++) a[m] = sm[SW(base + (m << SIG))];
    dft16<false>(a);
    float2 w;
    sincospif(-(float)s / (8.0f * (float)S), &w.y, &w.x);
    float2 w2 = cmulf(w, w);
    float2 w3 = cmulf(w2, w);
    float2 w4 = cmulf(w2, w2);
    // g = 0
    sm[SW(base)]              = a[0];
    sm[SW(base + (1 << SIG))] = cmulf(a[SIGTAB[1]], w);
    sm[SW(base + (2 << SIG))] = cmulf(a[SIGTAB[2]], w2);
    sm[SW(base + (3 << SIG))] = cmulf(a[SIGTAB[3]], w3);
    float2 bg = w4;
#pragma unroll
    for (int g = 1; g < 4; g++) {
        int u0 = g << 2;
        sm[SW(base + ((u0+0) << SIG))] = cmulf(a[SIGTAB[u0+0]], bg);
        sm[SW(base + ((u0+1) << SIG))] = cmulf(cmulf(a[SIGTAB[u0+1]], w),  bg);
        sm[SW(base + ((u0+2) << SIG))] = cmulf(cmulf(a[SIGTAB[u0+2]], w2), bg);
        sm[SW(base + ((u0+3) << SIG))] = cmulf(cmulf(a[SIGTAB[u0+3]], w3), bg);
        if (g < 3) bg = cmulf(bg, w4);
    }
}

// Inverse middle stage: pre-twiddle W^{-s*m} (conj base), conj-dft16, write back.
template<int SIG>
__device__ __forceinline__ void dit_stage(float2* sm, int t) {
    const int S = 1 << SIG;
    int s = t & (S - 1);
    int base = ((t >> SIG) << (SIG + 4)) | s;
    float2 w;
    sincospif((float)s / (8.0f * (float)S), &w.y, &w.x);  // conj twiddle
    float2 w2 = cmulf(w, w);
    float2 w3 = cmulf(w2, w);
    float2 w4 = cmulf(w2, w2);
    float2 a[16];
    a[0] = sm[SW(base)];
    a[1] = cmulf(sm[SW(base + (1 << SIG))], w);
    a[2] = cmulf(sm[SW(base + (2 << SIG))], w2);
    a[3] = cmulf(sm[SW(base + (3 << SIG))], w3);
    float2 bg = w4;
#pragma unroll
    for (int g = 1; g < 4; g++) {
        int m0 = g << 2;
        a[m0+0] = cmulf(sm[SW(base + ((m0+0) << SIG))], bg);
        a[m0+1] = cmulf(cmulf(sm[SW(base + ((m0+1) << SIG))], w),  bg);
        a[m0+2] = cmulf(cmulf(sm[SW(base + ((m0+2) << SIG))], w2), bg);
        a[m0+3] = cmulf(cmulf(sm[SW(base + ((m0+3) << SIG))], w3), bg);
        if (g < 3) bg = cmulf(bg, w4);
    }
    dft16<true>(a);
#pragma unroll
    for (int u = 0; u < 16; u++) sm[SW(base + (u << SIG))] = a[SIGTAB[u]];
}

// ---------------------------------------------------------------------------
// Main kernel: DIF forward (stage A from GMEM), fused radix4+pointwise+iradix4,
// inverse stages, final stage straight to GMEM. 6 barriers total.
// ---------------------------------------------------------------------------
__global__ __launch_bounds__(THREADS, 1)
void k_fftconv(const float* __restrict__ x, float* __restrict__ y) {
    extern __shared__ float2 sm[];
    const int t = threadIdx.x;
    const size_t row = (size_t)blockIdx.x * 2;
    const float* __restrict__ xa = x + row * L;
    const float* __restrict__ xb = xa + L;

    // ---- Stage A (DIF, S=1024): load straight from GMEM into registers ----
    {
        float2 a[16];
#pragma unroll
        for (int m = 0; m < 16; m++) {
            int i = t + (m << 10);
            a[m] = make_float2(xa[i], xb[i]);
        }
        dft16<false>(a);
        float2 w;
        sincospif(-(float)t / 8192.0f, &w.y, &w.x);
        float2 w2 = cmulf(w, w);
        float2 w3 = cmulf(w2, w);
        float2 w4 = cmulf(w2, w2);
        sm[SW(t)]             = a[0];
        sm[SW(t + (1<<10))]   = cmulf(a[SIGTAB[1]], w);
        sm[SW(t + (2<<10))]   = cmulf(a[SIGTAB[2]], w2);
        sm[SW(t + (3<<10))]   = cmulf(a[SIGTAB[3]], w3);
        float2 bg = w4;
#pragma unroll
        for (int g = 1; g < 4; g++) {
            int u0 = g << 2;
            sm[SW(t + ((u0+0)<<10))] = cmulf(a[SIGTAB[u0+0]], bg);
            sm[SW(t + ((u0+1)<<10))] = cmulf(cmulf(a[SIGTAB[u0+1]], w),  bg);
            sm[SW(t + ((u0+2)<<10))] = cmulf(cmulf(a[SIGTAB[u0+2]], w2), bg);
            sm[SW(t + ((u0+3)<<10))] = cmulf(cmulf(a[SIGTAB[u0+3]], w3), bg);
            if (g < 3) bg = cmulf(bg, w4);
        }
    }
    __syncthreads();

    dif_stage<6>(sm, t);   // stage B
    __syncthreads();
    dif_stage<2>(sm, t);   // stage C
    __syncthreads();

    // ---- Fused: forward radix-4 (stride 1) + pointwise H*Z + inverse radix-4 ----
    {
        const float4* __restrict__ hc4 = (const float4*)g_Hc;
#pragma unroll
        for (int p = 0; p < 4; p++) {
            int i0 = (t << 2) + (p << 12);
            float2 z0 = sm[SW(i0)];
            float2 z1 = sm[SW(i0 + 1)];
            float2 z2 = sm[SW(i0 + 2)];
            float2 z3 = sm[SW(i0 + 3)];
            dft4<false>(z0, z1, z2, z3);
            float4 hA = hc4[i0 >> 1];
            float4 hB = hc4[(i0 >> 1) + 1];
            z0 = cmulf(make_float2(hA.x, hA.y), z0);
            z1 = cmulf(make_float2(hA.z, hA.w), z1);
            z2 = cmulf(make_float2(hB.x, hB.y), z2);
            z3 = cmulf(make_float2(hB.z, hB.w), z3);
            dft4<true>(z0, z1, z2, z3);
            sm[SW(i0)]     = z0;
            sm[SW(i0 + 1)] = z1;
            sm[SW(i0 + 2)] = z2;
            sm[SW(i0 + 3)] = z3;
        }
    }
    __syncthreads();

    dit_stage<2>(sm, t);   // inverse stage C
    __syncthreads();
    dit_stage<6>(sm, t);   // inverse stage B
    __syncthreads();

    // ---- Inverse stage A (S=1024): write straight to GMEM ----
    {
        float2 w;
        sincospif((float)t / 8192.0f, &w.y, &w.x);  // conj twiddle
        float2 w2 = cmulf(w, w);
        float2 w3 = cmulf(w2, w);
        float2 w4 = cmulf(w2, w2);
        float2 a[16];
        a[0] = sm[SW(t)];
        a[1] = cmulf(sm[SW(t + (1<<10))], w);
        a[2] = cmulf(sm[SW(t + (2<<10))], w2);
        a[3] = cmulf(sm[SW(t + (3<<10))], w3);
        float2 bg = w4;
#pragma unroll
        for (int g = 1; g < 4; g++) {
            int m0 = g << 2;
            a[m0+0] = cmulf(sm[SW(t + ((m0+0)<<10))], bg);
            a[m0+1] = cmulf(cmulf(sm[SW(t + ((m0+1)<<10))], w),  bg);
            a[m0+2] = cmulf(cmulf(sm[SW(t + ((m0+2)<<10))], w2), bg);
            a[m0+3] = cmulf(cmulf(sm[SW(t + ((m0+3)<<10))], w3), bg);
            if (g < 3) bg = cmulf(bg, w4);
        }
        dft16<true>(a);
        float* __restrict__ ya = y + row * L;
        float* __restrict__ yb = ya + L;
#pragma unroll
        for (int u = 0; u < 16; u++) {
            float2 v = a[SIGTAB[u]];
            int i = t + (u << 10);
            ya[i] = v.x;
            yb[i] = v.y;
        }
    }
}

// ---------------------------------------------------------------------------
extern "C" void kernel_launch(void* const* d_in, const int* in_sizes, int n_in,
                              void* d_out, int out_size) {
    const float* x  = (const float*)d_in[0];
    const float* Lr = (const float*)d_in[1];
    const float* Li = (const float*)d_in[2];
    const float* wr = (const float*)d_in[3];
    const float* wi = (const float*)d_in[4];
    const float* dt = (const float*)d_in[5];
    float* y = (float*)d_out;

    cudaFuncSetAttribute(k_fftconv, cudaFuncAttributeMaxDynamicSharedMemorySize,
                         L * sizeof(float2));

    k_modes<<<1, NMODES>>>(Lr, Li, wr, wi, dt);
    k_hc<<<(L / 2 + 1 + 127) / 128, 128>>>();
    k_fftconv<<<(8 * 256) / 2, THREADS, L * sizeof(float2)>>>(x, y);
}

// round 6
// speedup vs baseline: 1.2501x; 1.1302x over previous
#include <cuda_runtime.h>
#include <math.h>

#define L       16384
#define NMODES  64
#define THREADS 512
#define SW(a) ((a) ^ (((a) >> 4) & 15))

__device__ float2 g_Hc[L];     // H[k]/L stored at scrambled position P(k)

// ---------------------------------------------------------------------------
// Packed f32x2 helpers
// ---------------------------------------------------------------------------
union F2U { float2 f; unsigned long long u; };

__device__ __forceinline__ float2 f2add(float2 a, float2 b) {
    F2U x, y, r; x.f = a; y.f = b;
    asm("add.rn.f32x2 %0, %1, %2;" : "=l"(r.u) : "l"(x.u), "l"(y.u));
    return r.f;
}
__device__ __forceinline__ float2 f2fma(float2 a, float2 b, float2 c) {
    F2U x, y, z, r; x.f = a; y.f = b; z.f = c;
    asm("fma.rn.f32x2 %0, %1, %2, %3;" : "=l"(r.u) : "l"(x.u), "l"(y.u), "l"(z.u));
    return r.f;
}
__device__ __forceinline__ float2 f2sub(float2 a, float2 b) {
    return f2fma(b, make_float2(-1.0f, -1.0f), a);
}
__device__ __forceinline__ float2 cmulf(float2 a, float2 b) {
    return make_float2(a.x*b.x - a.y*b.y, a.x*b.y + a.y*b.x);
}

// Scrambled position of frequency k under DIF(16,16,16,4):
// P(k) = 1024*k0 + 64*k1 + 4*k2 + k3,  k = k0 + 16k1 + 256k2 + 4096k3
__device__ __forceinline__ int scramble(int k) {
    return ((k & 15) << 10) | (((k >> 4) & 15) << 6) | (((k >> 8) & 15) << 2) | (k >> 12);
}

// ---------------------------------------------------------------------------
// Precompute (single kernel): per-mode constants in shared, then
// g_Hc[P(k)] = H[k]/L (no conj: second pass is a true inverse transform)
// ---------------------------------------------------------------------------
__global__ void k_hc(const float* __restrict__ Lr, const float* __restrict__ Li,
                     const float* __restrict__ wr, const float* __restrict__ wi,
                     const float* __restrict__ dtp) {
    __shared__ float4 md[NMODES];
    int t = threadIdx.x;
    if (t < NMODES) {
        int n = t;
        float dt = dtp[0];
        float lr = Lr[n], li = Li[n];
        float zr = dt * lr, zi = dt * li;
        float er = expf(zr);
        float sz, cz; sincosf(zi, &sz, &cz);
        float rr = er * cz, ri = er * sz;
        float rLm = expf(zr * (float)L);
        float Er = 1.0f, Ei = 0.0f;
        if (rLm > 1e-35f) {
            float sa, ca; sincosf(zi * (float)L, &sa, &ca);
            Er = 1.0f - rLm * ca; Ei = -rLm * sa;
        }
        float emr = rr - 1.0f, emi = ri;
        float il2 = 1.0f / (lr*lr + li*li);
        float qr = (emr*lr + emi*li) * il2;
        float qi = (emi*lr - emr*li) * il2;
        float Cr = wr[n]*qr - wi[n]*qi;
        float Ci = wr[n]*qi + wi[n]*qr;
        md[n] = make_float4(rr, ri, Cr*Er - Ci*Ei, Cr*Ei + Ci*Er);
    }
    __syncthreads();
    int kp = blockIdx.x * blockDim.x + t;
    if (kp > L / 2) return;
    float s, c;
    sincospif(2.0f * (float)kp / (float)L, &s, &c);
    float px = 0.f, py = 0.f, mx = 0.f, my = 0.f;
#pragma unroll 4
    for (int n = 0; n < NMODES; n++) {
        float4 m = md[n];
        float rc = m.x * c, rs = m.y * s;
        float rrs = m.x * s, ric = m.y * c;
        float dr = 1.0f - (rc + rs);
        float di = rrs - ric;
        float inv = 1.0f / (dr*dr + di*di);
        px += (m.z*dr + m.w*di) * inv;
        py += (m.w*dr - m.z*di) * inv;
        float dr2 = 1.0f - (rc - rs);
        float di2 = -rrs - ric;
        float inv2 = 1.0f / (dr2*dr2 + di2*di2);
        mx += (m.z*dr2 + m.w*di2) * inv2;
        my += (m.w*dr2 - m.z*di2) * inv2;
    }
    const float sc = 1.0f / (2.0f * (float)L);
    g_Hc[scramble(kp)]               = make_float2((px + mx) * sc, (py - my) * sc);
    g_Hc[scramble((L - kp) & (L-1))] = make_float2((px + mx) * sc, (my - py) * sc);
}

// ---------------------------------------------------------------------------
// Radix-4 / radix-16 butterflies, forward (INV=false) and conjugate (INV=true)
// ---------------------------------------------------------------------------
template<bool INV>
__device__ __forceinline__ void dft4(float2& a, float2& b, float2& c, float2& d) {
    float2 t0 = f2add(a, c);
    float2 t1 = f2sub(a, c);
    float2 t2 = f2add(b, d);
    float2 t3 = f2sub(b, d);
    a = f2add(t0, t2);
    c = f2sub(t0, t2);
    float2 t3r = INV ? make_float2(-t3.y, t3.x)     // +i*t3
                     : make_float2(t3.y, -t3.x);    // -i*t3
    b = f2add(t1, t3r);
    d = f2sub(t1, t3r);
}

// In-place DFT-16 (conjugate transform when INV). Output u lands at
// slot sig(u) = 4*(u&3) + (u>>2).
template<bool INV>
__device__ __forceinline__ void dft16(float2* a) {
    const float C1 = 0.92387953251128675613f;
    const float S1 = 0.38268343236508977173f;
    const float HS = 0.70710678118654752440f;
    const float sg = INV ? 1.0f : -1.0f;
    dft4<INV>(a[0], a[4], a[8],  a[12]);
    dft4<INV>(a[1], a[5], a[9],  a[13]);
    dft4<INV>(a[2], a[6], a[10], a[14]);
    dft4<INV>(a[3], a[7], a[11], a[15]);
    const float2 W1 = make_float2( C1, sg*S1);
    const float2 W2 = make_float2( HS, sg*HS);
    const float2 W3 = make_float2( S1, sg*C1);
    const float2 W6 = make_float2(-HS, sg*HS);
    const float2 W9 = make_float2(-C1, -sg*S1);
    a[5]  = cmulf(a[5],  W1);
    a[6]  = cmulf(a[6],  W2);
    a[7]  = cmulf(a[7],  W3);
    a[9]  = cmulf(a[9],  W2);
    a[10] = INV ? make_float2(-a[10].y, a[10].x)    // * (+i)
                : make_float2(a[10].y, -a[10].x);   // * (-i)
    a[11] = cmulf(a[11], W6);
    a[13] = cmulf(a[13], W3);
    a[14] = cmulf(a[14], W6);
    a[15] = cmulf(a[15], W9);
    dft4<INV>(a[0],  a[1],  a[2],  a[3]);
    dft4<INV>(a[4],  a[5],  a[6],  a[7]);
    dft4<INV>(a[8],  a[9],  a[10], a[11]);
    dft4<INV>(a[12], a[13], a[14], a[15]);
}

__device__ __constant__ int SIGTAB[16] = {0,4,8,12,1,5,9,13,2,6,10,14,3,7,11,15};

// DIF middle stage (forward) for ONE butterfly bf: read 16 @ base+(m<<SIG),
// dft16, output twiddle W^{s*u}, write back to the SAME slots.
template<int SIG>
__device__ __forceinline__ void dif_bf(float2* sm, int bf) {
    const int S = 1 << SIG;
    int s = bf & (S - 1);
    int base = ((bf >> SIG) << (SIG + 4)) | s;
    float2 a[16];
#pragma unroll
    for (int m = 0; m < 16; m++) a[m] = sm[SW(base + (m << SIG))];
    dft16<false>(a);
    float2 w;
    sincospif(-(float)s / (8.0f * (float)S), &w.y, &w.x);
    float2 w2 = cmulf(w, w);
    float2 w3 = cmulf(w2, w);
    float2 w4 = cmulf(w2, w2);
    sm[SW(base)]              = a[0];
    sm[SW(base + (1 << SIG))] = cmulf(a[SIGTAB[1]], w);
    sm[SW(base + (2 << SIG))] = cmulf(a[SIGTAB[2]], w2);
    sm[SW(base + (3 << SIG))] = cmulf(a[SIGTAB[3]], w3);
    float2 bg = w4;
#pragma unroll
    for (int g = 1; g < 4; g++) {
        int u0 = g << 2;
        sm[SW(base + ((u0+0) << SIG))] = cmulf(a[SIGTAB[u0+0]], bg);
        sm[SW(base + ((u0+1) << SIG))] = cmulf(cmulf(a[SIGTAB[u0+1]], w),  bg);
        sm[SW(base + ((u0+2) << SIG))] = cmulf(cmulf(a[SIGTAB[u0+2]], w2), bg);
        sm[SW(base + ((u0+3) << SIG))] = cmulf(cmulf(a[SIGTAB[u0+3]], w3), bg);
        if (g < 3) bg = cmulf(bg, w4);
    }
}

// Inverse middle stage for ONE butterfly: pre-twiddle W^{-s*m}, conj-dft16.
template<int SIG>
__device__ __forceinline__ void dit_bf(float2* sm, int bf) {
    const int S = 1 << SIG;
    int s = bf & (S - 1);
    int base = ((bf >> SIG) << (SIG + 4)) | s;
    float2 w;
    sincospif((float)s / (8.0f * (float)S), &w.y, &w.x);  // conj twiddle
    float2 w2 = cmulf(w, w);
    float2 w3 = cmulf(w2, w);
    float2 w4 = cmulf(w2, w2);
    float2 a[16];
    a[0] = sm[SW(base)];
    a[1] = cmulf(sm[SW(base + (1 << SIG))], w);
    a[2] = cmulf(sm[SW(base + (2 << SIG))], w2);
    a[3] = cmulf(sm[SW(base + (3 << SIG))], w3);
    float2 bg = w4;
#pragma unroll
    for (int g = 1; g < 4; g++) {
        int m0 = g << 2;
        a[m0+0] = cmulf(sm[SW(base + ((m0+0) << SIG))], bg);
        a[m0+1] = cmulf(cmulf(sm[SW(base + ((m0+1) << SIG))], w),  bg);
        a[m0+2] = cmulf(cmulf(sm[SW(base + ((m0+2) << SIG))], w2), bg);
        a[m0+3] = cmulf(cmulf(sm[SW(base + ((m0+3) << SIG))], w3), bg);
        if (g < 3) bg = cmulf(bg, w4);
    }
    dft16<true>(a);
#pragma unroll
    for (int u = 0; u < 16; u++) sm[SW(base + (u << SIG))] = a[SIGTAB[u]];
}

// Stage A forward for ONE butterfly: GMEM -> regs -> smem
__device__ __forceinline__ void stageA_fwd(float2* sm, int bf,
                                           const float* __restrict__ xa,
                                           const float* __restrict__ xb) {
    float2 a[16];
#pragma unroll
    for (int m = 0; m < 16; m++) {
        int i = bf + (m << 10);
        a[m] = make_float2(xa[i], xb[i]);
    }
    dft16<false>(a);
    float2 w;
    sincospif(-(float)bf / 8192.0f, &w.y, &w.x);
    float2 w2 = cmulf(w, w);
    float2 w3 = cmulf(w2, w);
    float2 w4 = cmulf(w2, w2);
    sm[SW(bf)]             = a[0];
    sm[SW(bf + (1<<10))]   = cmulf(a[SIGTAB[1]], w);
    sm[SW(bf + (2<<10))]   = cmulf(a[SIGTAB[2]], w2);
    sm[SW(bf + (3<<10))]   = cmulf(a[SIGTAB[3]], w3);
    float2 bg = w4;
#pragma unroll
    for (int g = 1; g < 4; g++) {
        int u0 = g << 2;
        sm[SW(bf + ((u0+0)<<10))] = cmulf(a[SIGTAB[u0+0]], bg);
        sm[SW(bf + ((u0+1)<<10))] = cmulf(cmulf(a[SIGTAB[u0+1]], w),  bg);
        sm[SW(bf + ((u0+2)<<10))] = cmulf(cmulf(a[SIGTAB[u0+2]], w2), bg);
        sm[SW(bf + ((u0+3)<<10))] = cmulf(cmulf(a[SIGTAB[u0+3]], w3), bg);
        if (g < 3) bg = cmulf(bg, w4);
    }
}

// Stage A inverse for ONE butterfly: smem -> regs -> GMEM
__device__ __forceinline__ void stageA_inv(const float2* sm, int bf,
                                           float* __restrict__ ya,
                                           float* __restrict__ yb) {
    float2 w;
    sincospif((float)bf / 8192.0f, &w.y, &w.x);  // conj twiddle
    float2 w2 = cmulf(w, w);
    float2 w3 = cmulf(w2, w);
    float2 w4 = cmulf(w2, w2);
    float2 a[16];
    a[0] = sm[SW(bf)];
    a[1] = cmulf(sm[SW(bf + (1<<10))], w);
    a[2] = cmulf(sm[SW(bf + (2<<10))], w2);
    a[3] = cmulf(sm[SW(bf + (3<<10))], w3);
    float2 bg = w4;
#pragma unroll
    for (int g = 1; g < 4; g++) {
        int m0 = g << 2;
        a[m0+0] = cmulf(sm[SW(bf + ((m0+0)<<10))], bg);
        a[m0+1] = cmulf(cmulf(sm[SW(bf + ((m0+1)<<10))], w),  bg);
        a[m0+2] = cmulf(cmulf(sm[SW(bf + ((m0+2)<<10))], w2), bg);
        a[m0+3] = cmulf(cmulf(sm[SW(bf + ((m0+3)<<10))], w3), bg);
        if (g < 3) bg = cmulf(bg, w4);
    }
    dft16<true>(a);
#pragma unroll
    for (int u = 0; u < 16; u++) {
        float2 v = a[SIGTAB[u]];
        int i = bf + (u << 10);
        ya[i] = v.x;
        yb[i] = v.y;
    }
}

// ---------------------------------------------------------------------------
// Main kernel: 512 threads, 2 sequential butterflies/thread (slot-partitioned
// in-place stages -> race-free within a stage), 7 barriers total.
// ---------------------------------------------------------------------------
__global__ __launch_bounds__(THREADS, 1)
void k_fftconv(const float* __restrict__ x, float* __restrict__ y) {
    extern __shared__ float2 sm[];
    const int t = threadIdx.x;
    const size_t row = (size_t)blockIdx.x * 2;
    const float* __restrict__ xa = x + row * L;
    const float* __restrict__ xb = xa + L;

    stageA_fwd(sm, t,       xa, xb);
    stageA_fwd(sm, t + 512, xa, xb);
    __syncthreads();

    dif_bf<6>(sm, t);
    dif_bf<6>(sm, t + 512);
    __syncthreads();
    dif_bf<2>(sm, t);
    dif_bf<2>(sm, t + 512);
    __syncthreads();

    // ---- Fused: forward radix-4 (stride 1) + pointwise H*Z + inverse radix-4 ----
    {
        const float4* __restrict__ hc4 = (const float4*)g_Hc;
#pragma unroll
        for (int p = 0; p < 8; p++) {
            int q = t + (p << 9);
            int i0 = q << 2;
            float2 z0 = sm[SW(i0)];
            float2 z1 = sm[SW(i0 + 1)];
            float2 z2 = sm[SW(i0 + 2)];
            float2 z3 = sm[SW(i0 + 3)];
            dft4<false>(z0, z1, z2, z3);
            float4 hA = hc4[q << 1];
            float4 hB = hc4[(q << 1) + 1];
            z0 = cmulf(make_float2(hA.x, hA.y), z0);
            z1 = cmulf(make_float2(hA.z, hA.w), z1);
            z2 = cmulf(make_float2(hB.x, hB.y), z2);
            z3 = cmulf(make_float2(hB.z, hB.w), z3);
            dft4<true>(z0, z1, z2, z3);
            sm[SW(i0)]     = z0;
            sm[SW(i0 + 1)] = z1;
            sm[SW(i0 + 2)] = z2;
            sm[SW(i0 + 3)] = z3;
        }
    }
    __syncthreads();

    dit_bf<2>(sm, t);
    dit_bf<2>(sm, t + 512);
    __syncthreads();
    dit_bf<6>(sm, t);
    dit_bf<6>(sm, t + 512);
    __syncthreads();

    float* __restrict__ ya = y + row * L;
    float* __restrict__ yb = ya + L;
    stageA_inv(sm, t,       ya, yb);
    stageA_inv(sm, t + 512, ya, yb);
}

// ---------------------------------------------------------------------------
extern "C" void kernel_launch(void* const* d_in, const int* in_sizes, int n_in,
                              void* d_out, int out_size) {
    const float* x  = (const float*)d_in[0];
    const float* Lr = (const float*)d_in[1];
    const float* Li = (const float*)d_in[2];
    const float* wr = (const float*)d_in[3];
    const float* wi = (const float*)d_in[4];
    const float* dt = (const float*)d_in[5];
    float* y = (float*)d_out;

    cudaFuncSetAttribute(k_fftconv, cudaFuncAttributeMaxDynamicSharedMemorySize,
                         L * sizeof(float2));

    k_hc<<<(L / 2 + 1 + 255) / 256, 256>>>(Lr, Li, wr, wi, dt);
    k_fftconv<<<(8 * 256) / 2, THREADS, L * sizeof(float2)>>>(x, y);
}

// round 7
// speedup vs baseline: 1.5954x; 1.2762x over previous
#include <cuda_runtime.h>
#include <math.h>

#define L       16384
#define NMODES  64
#define THREADS 512
#define SW(a) ((a) ^ (((a) >> 4) & 15))

__device__ float2 g_Hc[L];   // H[k]/L at position: block c=k0*16+k1, then q1*16+q0

// ---------------------------------------------------------------------------
union F2U { float2 f; unsigned long long u; };

__device__ __forceinline__ float2 f2add(float2 a, float2 b) {
    F2U x, y, r; x.f = a; y.f = b;
    asm("add.rn.f32x2 %0, %1, %2;" : "=l"(r.u) : "l"(x.u), "l"(y.u));
    return r.f;
}
__device__ __forceinline__ float2 f2fma(float2 a, float2 b, float2 c) {
    F2U x, y, z, r; x.f = a; y.f = b; z.f = c;
    asm("fma.rn.f32x2 %0, %1, %2, %3;" : "=l"(r.u) : "l"(x.u), "l"(y.u), "l"(z.u));
    return r.f;
}
__device__ __forceinline__ float2 f2sub(float2 a, float2 b) {
    return f2fma(b, make_float2(-1.0f, -1.0f), a);
}
__device__ __forceinline__ float2 cmulf(float2 a, float2 b) {
    return make_float2(a.x*b.x - a.y*b.y, a.x*b.y + a.y*b.x);
}
__device__ __forceinline__ float2 f2shfl_xor(float2 v, int m) {
    float2 r;
    r.x = __shfl_xor_sync(0xFFFFFFFFu, v.x, m);
    r.y = __shfl_xor_sync(0xFFFFFFFFu, v.y, m);
    return r;
}

// digit-swap permutation of dft16 outputs (involution)
__host__ __device__ constexpr int sigc(int u) { return 4 * (u & 3) + (u >> 2); }

// position of frequency k: k = k0 + 16k1 + 256q0 + 4096q1 (q = q0+16q1 = 64-DFT freq)
// pos = k0*1024 + k1*64 + q1*16 + q0
__device__ __forceinline__ int scramble(int k) {
    return ((k & 15) << 10) | (((k >> 4) & 15) << 6)
         | (((k >> 12) & 3) << 4) | ((k >> 8) & 15);
}

// ---------------------------------------------------------------------------
// Precompute: g_Hc[scramble(k)] = H[k]/L
// ---------------------------------------------------------------------------
__global__ void k_hc(const float* __restrict__ Lr, const float* __restrict__ Li,
                     const float* __restrict__ wr, const float* __restrict__ wi,
                     const float* __restrict__ dtp) {
    __shared__ float4 md[NMODES];
    int t = threadIdx.x;
    if (t < NMODES) {
        int n = t;
        float dt = dtp[0];
        float lr = Lr[n], li = Li[n];
        float zr = dt * lr, zi = dt * li;
        float er = expf(zr);
        float sz, cz; sincosf(zi, &sz, &cz);
        float rr = er * cz, ri = er * sz;
        float rLm = expf(zr * (float)L);
        float Er = 1.0f, Ei = 0.0f;
        if (rLm > 1e-35f) {
            float sa, ca; sincosf(zi * (float)L, &sa, &ca);
            Er = 1.0f - rLm * ca; Ei = -rLm * sa;
        }
        float emr = rr - 1.0f, emi = ri;
        float il2 = 1.0f / (lr*lr + li*li);
        float qr = (emr*lr + emi*li) * il2;
        float qi = (emi*lr - emr*li) * il2;
        float Cr = wr[n]*qr - wi[n]*qi;
        float Ci = wr[n]*qi + wi[n]*qr;
        md[n] = make_float4(rr, ri, Cr*Er - Ci*Ei, Cr*Ei + Ci*Er);
    }
    __syncthreads();
    int kp = blockIdx.x * blockDim.x + t;
    if (kp > L / 2) return;
    float s, c;
    sincospif(2.0f * (float)kp / (float)L, &s, &c);
    float px = 0.f, py = 0.f, mx = 0.f, my = 0.f;
#pragma unroll 4
    for (int n = 0; n < NMODES; n++) {
        float4 m = md[n];
        float rc = m.x * c, rs = m.y * s;
        float rrs = m.x * s, ric = m.y * c;
        float dr = 1.0f - (rc + rs);
        float di = rrs - ric;
        float inv = 1.0f / (dr*dr + di*di);
        px += (m.z*dr + m.w*di) * inv;
        py += (m.w*dr - m.z*di) * inv;
        float dr2 = 1.0f - (rc - rs);
        float di2 = -rrs - ric;
        float inv2 = 1.0f / (dr2*dr2 + di2*di2);
        mx += (m.z*dr2 + m.w*di2) * inv2;
        my += (m.w*dr2 - m.z*di2) * inv2;
    }
    const float sc = 1.0f / (2.0f * (float)L);
    g_Hc[scramble(kp)]               = make_float2((px + mx) * sc, (py - my) * sc);
    g_Hc[scramble((L - kp) & (L-1))] = make_float2((px + mx) * sc, (my - py) * sc);
}

// ---------------------------------------------------------------------------
// Butterflies
// ---------------------------------------------------------------------------
template<bool INV>
__device__ __forceinline__ void dft4(float2& a, float2& b, float2& c, float2& d) {
    float2 t0 = f2add(a, c);
    float2 t1 = f2sub(a, c);
    float2 t2 = f2add(b, d);
    float2 t3 = f2sub(b, d);
    a = f2add(t0, t2);
    c = f2sub(t0, t2);
    float2 t3r = INV ? make_float2(-t3.y, t3.x) : make_float2(t3.y, -t3.x);
    b = f2add(t1, t3r);
    d = f2sub(t1, t3r);
}

// In-place DFT-16 (conj when INV). Digit u's output lands at slot sigc(u).
template<bool INV>
__device__ __forceinline__ void dft16(float2* a) {
    const float C1 = 0.92387953251128675613f;
    const float S1 = 0.38268343236508977173f;
    const float HS = 0.70710678118654752440f;
    const float sg = INV ? 1.0f : -1.0f;
    dft4<INV>(a[0], a[4], a[8],  a[12]);
    dft4<INV>(a[1], a[5], a[9],  a[13]);
    dft4<INV>(a[2], a[6], a[10], a[14]);
    dft4<INV>(a[3], a[7], a[11], a[15]);
    const float2 W1 = make_float2( C1, sg*S1);
    const float2 W2 = make_float2( HS, sg*HS);
    const float2 W3 = make_float2( S1, sg*C1);
    const float2 W6 = make_float2(-HS, sg*HS);
    const float2 W9 = make_float2(-C1, -sg*S1);
    a[5]  = cmulf(a[5],  W1);
    a[6]  = cmulf(a[6],  W2);
    a[7]  = cmulf(a[7],  W3);
    a[9]  = cmulf(a[9],  W2);
    a[10] = INV ? make_float2(-a[10].y, a[10].x) : make_float2(a[10].y, -a[10].x);
    a[11] = cmulf(a[11], W6);
    a[13] = cmulf(a[13], W3);
    a[14] = cmulf(a[14], W6);
    a[15] = cmulf(a[15], W9);
    dft4<INV>(a[0],  a[1],  a[2],  a[3]);
    dft4<INV>(a[4],  a[5],  a[6],  a[7]);
    dft4<INV>(a[8],  a[9],  a[10], a[11]);
    dft4<INV>(a[12], a[13], a[14], a[15]);
}

// DIF middle stage (forward), one butterfly: same-slot in-place.
template<int SIG>
__device__ __forceinline__ void dif_bf(float2* sm, int bf) {
    const int S = 1 << SIG;
    int s = bf & (S - 1);
    int base = ((bf >> SIG) << (SIG + 4)) | s;
    float2 a[16];
#pragma unroll
    for (int m = 0; m < 16; m++) a[m] = sm[SW(base + (m << SIG))];
    dft16<false>(a);
    float2 w;
    sincospif(-(float)s / (8.0f * (float)S), &w.y, &w.x);
    float2 w2 = cmulf(w, w);
    float2 w3 = cmulf(w2, w);
    float2 w4 = cmulf(w2, w2);
    sm[SW(base)]              = a[0];
    sm[SW(base + (1 << SIG))] = cmulf(a[sigc(1)], w);
    sm[SW(base + (2 << SIG))] = cmulf(a[sigc(2)], w2);
    sm[SW(base + (3 << SIG))] = cmulf(a[sigc(3)], w3);
    float2 bg = w4;
#pragma unroll
    for (int g = 1; g < 4; g++) {
        int u0 = g << 2;
        sm[SW(base + ((u0+0) << SIG))] = cmulf(a[sigc(u0+0)], bg);
        sm[SW(base + ((u0+1) << SIG))] = cmulf(cmulf(a[sigc(u0+1)], w),  bg);
        sm[SW(base + ((u0+2) << SIG))] = cmulf(cmulf(a[sigc(u0+2)], w2), bg);
        sm[SW(base + ((u0+3) << SIG))] = cmulf(cmulf(a[sigc(u0+3)], w3), bg);
        if (g < 3) bg = cmulf(bg, w4);
    }
}

// Inverse middle stage, one butterfly.
template<int SIG>
__device__ __forceinline__ void dit_bf(float2* sm, int bf) {
    const int S = 1 << SIG;
    int s = bf & (S - 1);
    int base = ((bf >> SIG) << (SIG + 4)) | s;
    float2 w;
    sincospif((float)s / (8.0f * (float)S), &w.y, &w.x);
    float2 w2 = cmulf(w, w);
    float2 w3 = cmulf(w2, w);
    float2 w4 = cmulf(w2, w2);
    float2 a[16];
    a[0] = sm[SW(base)];
    a[1] = cmulf(sm[SW(base + (1 << SIG))], w);
    a[2] = cmulf(sm[SW(base + (2 << SIG))], w2);
    a[3] = cmulf(sm[SW(base + (3 << SIG))], w3);
    float2 bg = w4;
#pragma unroll
    for (int g = 1; g < 4; g++) {
        int m0 = g << 2;
        a[m0+0] = cmulf(sm[SW(base + ((m0+0) << SIG))], bg);
        a[m0+1] = cmulf(cmulf(sm[SW(base + ((m0+1) << SIG))], w),  bg);
        a[m0+2] = cmulf(cmulf(sm[SW(base + ((m0+2) << SIG))], w2), bg);
        a[m0+3] = cmulf(cmulf(sm[SW(base + ((m0+3) << SIG))], w3), bg);
        if (g < 3) bg = cmulf(bg, w4);
    }
    dft16<true>(a);
#pragma unroll
    for (int u = 0; u < 16; u++) sm[SW(base + (u << SIG))] = a[sigc(u)];
}

// Stage A forward: GMEM -> regs -> smem
__device__ __forceinline__ void stageA_fwd(float2* sm, int bf,
                                           const float* __restrict__ xa,
                                           const float* __restrict__ xb) {
    float2 a[16];
#pragma unroll
    for (int m = 0; m < 16; m++) {
        int i = bf + (m << 10);
        a[m] = make_float2(xa[i], xb[i]);
    }
    dft16<false>(a);
    float2 w;
    sincospif(-(float)bf / 8192.0f, &w.y, &w.x);
    float2 w2 = cmulf(w, w);
    float2 w3 = cmulf(w2, w);
    float2 w4 = cmulf(w2, w2);
    sm[SW(bf)]             = a[0];
    sm[SW(bf + (1<<10))]   = cmulf(a[sigc(1)], w);
    sm[SW(bf + (2<<10))]   = cmulf(a[sigc(2)], w2);
    sm[SW(bf + (3<<10))]   = cmulf(a[sigc(3)], w3);
    float2 bg = w4;
#pragma unroll
    for (int g = 1; g < 4; g++) {
        int u0 = g << 2;
        sm[SW(bf + ((u0+0)<<10))] = cmulf(a[sigc(u0+0)], bg);
        sm[SW(bf + ((u0+1)<<10))] = cmulf(cmulf(a[sigc(u0+1)], w),  bg);
        sm[SW(bf + ((u0+2)<<10))] = cmulf(cmulf(a[sigc(u0+2)], w2), bg);
        sm[SW(bf + ((u0+3)<<10))] = cmulf(cmulf(a[sigc(u0+3)], w3), bg);
        if (g < 3) bg = cmulf(bg, w4);
    }
}

// Stage A inverse: smem -> regs -> GMEM
__device__ __forceinline__ void stageA_inv(const float2* sm, int bf,
                                           float* __restrict__ ya,
                                           float* __restrict__ yb) {
    float2 w;
    sincospif((float)bf / 8192.0f, &w.y, &w.x);
    float2 w2 = cmulf(w, w);
    float2 w3 = cmulf(w2, w);
    float2 w4 = cmulf(w2, w2);
    float2 a[16];
    a[0] = sm[SW(bf)];
    a[1] = cmulf(sm[SW(bf + (1<<10))], w);
    a[2] = cmulf(sm[SW(bf + (2<<10))], w2);
    a[3] = cmulf(sm[SW(bf + (3<<10))], w3);
    float2 bg = w4;
#pragma unroll
    for (int g = 1; g < 4; g++) {
        int m0 = g << 2;
        a[m0+0] = cmulf(sm[SW(bf + ((m0+0)<<10))], bg);
        a[m0+1] = cmulf(cmulf(sm[SW(bf + ((m0+1)<<10))], w),  bg);
        a[m0+2] = cmulf(cmulf(sm[SW(bf + ((m0+2)<<10))], w2), bg);
        a[m0+3] = cmulf(cmulf(sm[SW(bf + ((m0+3)<<10))], w3), bg);
        if (g < 3) bg = cmulf(bg, w4);
    }
    dft16<true>(a);
#pragma unroll
    for (int u = 0; u < 16; u++) {
        float2 v = a[sigc(u)];
        int i = bf + (u << 10);
        ya[i] = v.x;
        yb[i] = v.y;
    }
}

// ---------------------------------------------------------------------------
// Register-resident middle for one 64-block, owned by a 4-lane group.
// Lane role s holds elements {c*64 + 4*m + s}. Does: radix-16 (stage C, in
// thread) -> cross-lane radix-4 (shfl) -> pointwise H -> inverse radix-4 ->
// conj twiddle -> conj radix-16 -> write back to the SAME slots.
// ---------------------------------------------------------------------------
__device__ __forceinline__ void mid64(float2* sm, int c, int s, int q1s) {
    const int base = c * 64 + s;
    float2 a[16];
#pragma unroll
    for (int m = 0; m < 16; m++) a[m] = sm[SW(base + 4*m)];
    dft16<false>(a);

    // stage-C output twiddle: a[sigc(u)] *= w1^u, w1 = exp(-i*pi*s/32)
    float2 w1;
    sincospif(-(float)s / 32.0f, &w1.y, &w1.x);
    {
        float2 w2 = cmulf(w1, w1);
        float2 w3 = cmulf(w2, w1);
        float2 w4 = cmulf(w2, w2);
        a[sigc(1)] = cmulf(a[sigc(1)], w1);
        a[sigc(2)] = cmulf(a[sigc(2)], w2);
        a[sigc(3)] = cmulf(a[sigc(3)], w3);
        float2 bg = w4;
#pragma unroll
        for (int g = 1; g < 4; g++) {
            int u0 = g << 2;
            a[sigc(u0+0)] = cmulf(a[sigc(u0+0)], bg);
            a[sigc(u0+1)] = cmulf(cmulf(a[sigc(u0+1)], w1), bg);
            a[sigc(u0+2)] = cmulf(cmulf(a[sigc(u0+2)], w2), bg);
            a[sigc(u0+3)] = cmulf(cmulf(a[sigc(u0+3)], w3), bg);
            if (g < 3) bg = cmulf(bg, w4);
        }
    }

    // forward cross-lane radix-4 (over s), per register. Lane ends with q1 = bitrev2(s).
#pragma unroll
    for (int r = 0; r < 16; r++) {
        float2 v = a[r];
        float2 tt = f2shfl_xor(v, 2);
        float2 u;
        if (s & 2) {
            u = f2sub(tt, v);
            if (s & 1) u = make_float2(u.y, -u.x);   // * (-i)
        } else {
            u = f2add(v, tt);
        }
        float2 t2 = f2shfl_xor(u, 1);
        a[r] = (s & 1) ? f2sub(t2, u) : f2add(u, t2);
    }

    // pointwise: new a[u] = h[u] * old a[sigc(u)]  (sigc is an involution)
    {
        const float4* __restrict__ h4 = (const float4*)g_Hc + ((c * 64 + q1s * 16) >> 1);
        float2 h[16];
#pragma unroll
        for (int i = 0; i < 8; i++) {
            float4 v = h4[i];
            h[2*i]   = make_float2(v.x, v.y);
            h[2*i+1] = make_float2(v.z, v.w);
        }
        // fixed points of sigc: 0,5,10,15
        a[0]  = cmulf(h[0],  a[0]);
        a[5]  = cmulf(h[5],  a[5]);
        a[10] = cmulf(h[10], a[10]);
        a[15] = cmulf(h[15], a[15]);
        // 2-cycles: (1,4)(2,8)(3,12)(6,9)(7,13)(11,14)
#pragma unroll
        for (int p = 0; p < 6; p++) {
            const int U[6] = {1, 2, 3, 6, 7, 11};
            int u = U[p], v = sigc(u);
            float2 tmp = a[u];
            a[u] = cmulf(h[u], a[v]);
            a[v] = cmulf(h[v], tmp);
        }
    }

    // inverse cross-lane radix-4, per register. Lane ends with time-role s.
#pragma unroll
    for (int r = 0; r < 16; r++) {
        float2 v = a[r];
        float2 tt = f2shfl_xor(v, 1);
        float2 u = (s & 1) ? f2sub(tt, v) : f2add(v, tt);
        if ((s & 3) == 3) u = make_float2(-u.y, u.x);   // * (+i)
        float2 t2 = f2shfl_xor(u, 2);
        a[r] = (s & 2) ? f2sub(t2, u) : f2add(u, t2);
    }

    // conj stage-C twiddle: a[u] *= conj(w1)^u  (a is in natural q0 order now)
    {
        float2 w1c = make_float2(w1.x, -w1.y);
        float2 w2 = cmulf(w1c, w1c);
        float2 w3 = cmulf(w2, w1c);
        float2 w4 = cmulf(w2, w2);
        a[1] = cmulf(a[1], w1c);
        a[2] = cmulf(a[2], w2);
        a[3] = cmulf(a[3], w3);
        float2 bg = w4;
#pragma unroll
        for (int g = 1; g < 4; g++) {
            int m0 = g << 2;
            a[m0+0] = cmulf(a[m0+0], bg);
            a[m0+1] = cmulf(cmulf(a[m0+1], w1c), bg);
            a[m0+2] = cmulf(cmulf(a[m0+2], w2),  bg);
            a[m0+3] = cmulf(cmulf(a[m0+3], w3),  bg);
            if (g < 3) bg = cmulf(bg, w4);
        }
    }
    dft16<true>(a);
#pragma unroll
    for (int m = 0; m < 16; m++) sm[SW(base + 4*m)] = a[sigc(m)];
}

// ---------------------------------------------------------------------------
// Main kernel: 4 barriers total.
// ---------------------------------------------------------------------------
__global__ __launch_bounds__(THREADS, 1)
void k_fftconv(const float* __restrict__ x, float* __restrict__ y) {
    extern __shared__ float2 sm[];
    const int t = threadIdx.x;
    const int lane = t & 31;
    const int s = lane & 3;
    const int q1s = ((s & 1) << 1) | (s >> 1);
    const int cbase = (t >> 5) * 8 + (lane >> 2);   // warp*8 + group
    const size_t row = (size_t)blockIdx.x * 2;
    const float* __restrict__ xa = x + row * L;
    const float* __restrict__ xb = xa + L;

    stageA_fwd(sm, t,       xa, xb);
    stageA_fwd(sm, t + 512, xa, xb);
    __syncthreads();

    dif_bf<6>(sm, t);
    dif_bf<6>(sm, t + 512);
    __syncthreads();

    mid64(sm, cbase,       s, q1s);
    mid64(sm, cbase + 128, s, q1s);
    __syncthreads();

    dit_bf<6>(sm, t);
    dit_bf<6>(sm, t + 512);
    __syncthreads();

    float* __restrict__ ya = y + row * L;
    float* __restrict__ yb = ya + L;
    stageA_inv(sm, t,       ya, yb);
    stageA_inv(sm, t + 512, ya, yb);
}

// ---------------------------------------------------------------------------
extern "C" void kernel_launch(void* const* d_in, const int* in_sizes, int n_in,
                              void* d_out, int out_size) {
    const float* x  = (const float*)d_in[0];
    const float* Lr = (const float*)d_in[1];
    const float* Li = (const float*)d_in[2];
    const float* wr = (const float*)d_in[3];
    const float* wi = (const float*)d_in[4];
    const float* dt = (const float*)d_in[5];
    float* y = (float*)d_out;

    cudaFuncSetAttribute(k_fftconv, cudaFuncAttributeMaxDynamicSharedMemorySize,
                         L * sizeof(float2));

    k_hc<<<(L / 2 + 1 + 255) / 256, 256>>>(Lr, Li, wr, wi, dt);
    k_fftconv<<<(8 * 256) / 2, THREADS, L * sizeof(float2)>>>(x, y);
}